// round 16
// baseline (speedup 1.0000x reference)
#include <cuda_runtime.h>
#include <cuda_fp16.h>
#include <cstdint>

#define TPB 256
#define NWARP 8
#define EPW 64
#define TILE_E (NWARP * EPW)   // 512
#define EGRID 152
#define MAXN 50000

// Per-node precomputed projections in FP16, COLUMN-PERMUTED:
// slice0 [0:32)  = nf@We1[0:128]+be1 (src)
// slice1 [32:64) = nf@We1[128:256]   (dst)
// slice2 [64:128)= nf@Wn1[0:128]+bn1 (pre2)
__device__ __align__(16) __half g_P[MAXN * 128];

// Pre-packed weight images (bit-identical to the smem layouts, pitches incl.)
__device__ __align__(16) uint32_t g_Wpre[128 * 68];  // precompute [128 n][68 w]
__device__ __align__(16) uint32_t g_W1p[32 * 36];
__device__ __align__(16) uint32_t g_W2p[128 * 20];
__device__ __align__(16) uint32_t g_W3p[64 * 68];
__device__ __align__(16) uint32_t g_W4p[128 * 36];

// ------------------------------- helpers ----------------------------------
__device__ __forceinline__ uint32_t h2pack(float lo, float hi) {
    uint32_t r;  // cvt.rn.f16x2.f32 d, a, b -> d.hi = a, d.lo = b
    asm("cvt.rn.f16x2.f32 %0, %1, %2;" : "=r"(r) : "f"(hi), "f"(lo));
    return r;
}
__device__ __forceinline__ uint32_t h2relu(float c0, float c1) {
    return h2pack(fmaxf(c0, 0.f), fmaxf(c1, 0.f));
}
__device__ __forceinline__ void red4(float* p, float a, float b, float c, float d) {
    asm volatile("red.global.add.v4.f32 [%0], {%1,%2,%3,%4};"
                 :: "l"(p), "f"(a), "f"(b), "f"(c), "f"(d) : "memory");
}
// D(16x8,f32) += A(16x16,f16) @ B(16x8,f16)
__device__ __forceinline__ void mma16(float* c, uint32_t a0, uint32_t a1,
                                      uint32_t a2, uint32_t a3,
                                      uint32_t b0, uint32_t b1) {
    asm volatile("mma.sync.aligned.m16n8k16.row.col.f32.f16.f16.f32 "
                 "{%0,%1,%2,%3}, {%4,%5,%6,%7}, {%8,%9}, {%0,%1,%2,%3};"
                 : "+f"(c[0]), "+f"(c[1]), "+f"(c[2]), "+f"(c[3])
                 : "r"(a0), "r"(a1), "r"(a2), "r"(a3), "r"(b0), "r"(b1));
}

// ---------------------------------------------------------------------------
// Pack kernel: one-time scattered transpose + f16 pack of all weights.
// ---------------------------------------------------------------------------
__global__ void __launch_bounds__(256) pack_weights_kernel(
    const float* __restrict__ We1,
    const float* __restrict__ We2,
    const float* __restrict__ Wn1,
    const float* __restrict__ Wn2)
{
    const int tid = blockIdx.x * 256 + threadIdx.x;
    const int stride = gridDim.x * 256;

    for (int i = tid; i < 128 * 64; i += stride) {          // precompute block
        int n = i >> 6, w = i & 63;
        float lo, hi;
        if (n < 32)      { lo = We1[(2*w)*32 + n];         hi = We1[(2*w+1)*32 + n]; }
        else if (n < 64) { lo = We1[(128+2*w)*32 + n-32];  hi = We1[(128+2*w+1)*32 + n-32]; }
        else             { lo = Wn1[(2*w)*64 + n-64];      hi = Wn1[(2*w+1)*64 + n-64]; }
        g_Wpre[n*68 + w] = h2pack(lo, hi);
    }
    const float* W = We1 + 256 * 32;
    for (int i = tid; i < 32 * 32; i += stride) {
        int n = i >> 5, w = i & 31;
        g_W1p[n*36 + w] = h2pack(W[(2*w)*32 + n], W[(2*w+1)*32 + n]);
    }
    for (int i = tid; i < 128 * 16; i += stride) {
        int n = i >> 4, w = i & 15;
        g_W2p[n*20 + w] = h2pack(We2[(2*w)*128 + n], We2[(2*w+1)*128 + n]);
    }
    const float* W3 = Wn1 + 128 * 64;
    for (int i = tid; i < 64 * 64; i += stride) {
        int n = i >> 6, w = i & 63;
        g_W3p[n*68 + w] = h2pack(W3[(2*w)*64 + n], W3[(2*w+1)*64 + n]);
    }
    for (int i = tid; i < 128 * 32; i += stride) {
        int n = i >> 5, w = i & 31;
        g_W4p[n*36 + w] = h2pack(Wn2[(2*w)*128 + n], Wn2[(2*w+1)*128 + n]);
    }
}

// ---------------------------------------------------------------------------
// Precompute via mma16 (R15 version, unchanged): 32 nodes/warp, 256/CTA.
// ---------------------------------------------------------------------------
#define P_TPB 256
#define P_WSMEM 8704
#define P_OFF_B 34816
#define P_OFF_SCR 35328
#define P_SMEM (P_OFF_SCR + 8 * P_WSMEM)   // 104960

__global__ void __launch_bounds__(P_TPB, 1) precompute_mma_kernel(
    const float* __restrict__ nf,
    const float* __restrict__ be1,
    const float* __restrict__ bn1,
    float* __restrict__ out, int Nn)
{
    extern __shared__ char sm[];
    uint32_t* Wp = (uint32_t*)sm;
    float* bias  = (float*)(sm + P_OFF_B);

    const int tid = threadIdx.x;
    {
        const uint4* src = (const uint4*)g_Wpre;
        uint4* dst = (uint4*)Wp;
        for (int i = tid; i < (128 * 68) / 4; i += P_TPB) dst[i] = src[i];
    }
    if (tid < 128)
        bias[tid] = (tid < 32) ? be1[tid] : ((tid < 64) ? 0.f : bn1[tid - 64]);
    __syncthreads();

    const int lane = tid & 31, wid = tid >> 5;
    const int g = lane >> 2, q = lane & 3;
    uint32_t* buf = (uint32_t*)(sm + P_OFF_SCR + wid * P_WSMEM);

    const int nb = blockIdx.x * 256 + wid * 32;

    #pragma unroll
    for (int it = 0; it < 32; it++) {
        int idx = it * 32 + lane;
        int row = idx >> 5, c = idx & 31;
        int n = nb + row;
        if (n < Nn) {
            float4 v = *(const float4*)&nf[(size_t)n * 128 + 4 * c];
            *(float4*)&out[(size_t)n * 128 + 4 * c] = v;
            uint2 w = { h2pack(v.x, v.y), h2pack(v.z, v.w) };
            *(uint2*)&buf[row * 68 + 2 * c] = w;
        } else {
            *(uint2*)&buf[row * 68 + 2 * c] = make_uint2(0, 0);
        }
    }
    __syncwarp();

    float c[2][16][4];
    #pragma unroll
    for (int nt = 0; nt < 16; nt++) {
        float2 b = *(const float2*)&bias[8 * nt + 2 * q];
        #pragma unroll
        for (int mt = 0; mt < 2; mt++) {
            c[mt][nt][0] = b.x; c[mt][nt][1] = b.y;
            c[mt][nt][2] = b.x; c[mt][nt][3] = b.y;
        }
    }
    #pragma unroll
    for (int kt = 0; kt < 8; kt++) {
        uint32_t a[2][4];
        #pragma unroll
        for (int mt = 0; mt < 2; mt++) {
            int r0 = (16*mt + g) * 68, r1 = (16*mt + 8 + g) * 68;
            a[mt][0] = buf[r0 + 8*kt + q];
            a[mt][1] = buf[r1 + 8*kt + q];
            a[mt][2] = buf[r0 + 8*kt + q + 4];
            a[mt][3] = buf[r1 + 8*kt + q + 4];
        }
        #pragma unroll
        for (int nt = 0; nt < 16; nt++) {
            uint32_t b0 = Wp[(8*nt+g)*68 + 8*kt + q];
            uint32_t b1 = Wp[(8*nt+g)*68 + 8*kt + q + 4];
            mma16(c[0][nt], a[0][0],a[0][1],a[0][2],a[0][3], b0, b1);
            mma16(c[1][nt], a[1][0],a[1][1],a[1][2],a[1][3], b0, b1);
        }
    }
    #pragma unroll
    for (int nt = 0; nt < 16; nt++) {
        int word = (nt < 4)  ? (q*4 + nt)
                 : (nt < 8)  ? (16 + q*4 + (nt - 4))
                 :             (32 + q*8 + (nt - 8));
        #pragma unroll
        for (int mt = 0; mt < 2; mt++) {
            int n0 = nb + 16*mt + g, n1 = nb + 16*mt + 8 + g;
            if (n0 < Nn)
                ((uint32_t*)&g_P[(size_t)n0 * 128])[word] = h2pack(c[mt][nt][0], c[mt][nt][1]);
            if (n1 < Nn)
                ((uint32_t*)&g_P[(size_t)n1 * 128])[word] = h2pack(c[mt][nt][2], c[mt][nt][3]);
        }
    }
}

// ---------------------------------------------------------------------------
// Edge kernel: persistent, 8 warps x 64 edges (M=64 halves weight-LDS/edge),
// 1 CTA/SM. fp16 mma; N chunked to 16 cols in L2/L4 to bound registers.
// ---------------------------------------------------------------------------
#define OFF_W1  0            // [32 n][36 w]  -> 4608 B
#define OFF_W2  4608         // [128][20]     -> 10240 B
#define OFF_W3  14848        // [64][68]      -> 17408 B
#define OFF_W4  32256        // [128][36]     -> 18432 B
#define OFF_BE2 50688
#define OFF_BN2 51200
#define OFF_SCR 51712
#define WS_BYTES 9216        // per-warp: ef f16 [64][36] / scatter f16 [64][8]
#define SM_TOTAL (OFF_SCR + NWARP * WS_BYTES)   // 125440

__global__ void __launch_bounds__(TPB, 1) edge_mma_kernel(
    const float* __restrict__ ef,
    const int*   __restrict__ eidx,
    const float* __restrict__ be2,
    const float* __restrict__ bn2,
    float* __restrict__ out, int E, int ntiles)
{
    extern __shared__ char sm[];
    uint32_t* W1s = (uint32_t*)(sm + OFF_W1);
    uint32_t* W2s = (uint32_t*)(sm + OFF_W2);
    uint32_t* W3s = (uint32_t*)(sm + OFF_W3);
    uint32_t* W4s = (uint32_t*)(sm + OFF_W4);
    float* be2s = (float*)(sm + OFF_BE2);
    float* bn2s = (float*)(sm + OFF_BN2);

    const int tid = threadIdx.x;
    {
        const uint4* s1 = (const uint4*)g_W1p;
        const uint4* s2 = (const uint4*)g_W2p;
        const uint4* s3 = (const uint4*)g_W3p;
        const uint4* s4 = (const uint4*)g_W4p;
        for (int i = tid; i < 288;  i += TPB) ((uint4*)(sm + OFF_W1))[i] = s1[i];
        for (int i = tid; i < 640;  i += TPB) ((uint4*)(sm + OFF_W2))[i] = s2[i];
        for (int i = tid; i < 1088; i += TPB) ((uint4*)(sm + OFF_W3))[i] = s3[i];
        for (int i = tid; i < 1152; i += TPB) ((uint4*)(sm + OFF_W4))[i] = s4[i];
    }
    if (tid < 128) { be2s[tid] = be2[tid]; bn2s[tid] = bn2[tid]; }
    __syncthreads();

    const int lane = tid & 31, wid = tid >> 5;
    const int g = lane >> 2, q = lane & 3;
    const unsigned F = 0xFFFFFFFFu;
    uint32_t* buf = (uint32_t*)(sm + OFF_SCR + wid * WS_BYTES);

    for (int t = blockIdx.x; t < ntiles; t += gridDim.x) {
        const int eb = t * TILE_E + wid * EPW;

        int sidx[8], didx[8];
        #pragma unroll
        for (int m = 0; m < 8; m++) {
            int r = eb + 16 * (m >> 1) + 8 * (m & 1) + g;
            r = (r < E) ? r : (E - 1);
            sidx[m] = eidx[r];
            didx[m] = eidx[E + r];
        }
        int r0c = eb + lane;        r0c = (r0c < E) ? r0c : (E - 1);
        int r1c = eb + 32 + lane;   r1c = (r1c < E) ? r1c : (E - 1);
        const int dl0 = eidx[E + r0c];
        const int dl1 = eidx[E + r1c];

        // ======== L1 init: c1 = pre1 =======================================
        float c1[4][4][4];
        #pragma unroll
        for (int m = 0; m < 8; m++) {
            const int mt = m >> 1, h = m & 1;
            uint4 us = *(const uint4*)&g_P[(size_t)sidx[m] * 128 + q * 8];
            uint4 ud = *(const uint4*)&g_P[(size_t)didx[m] * 128 + 32 + q * 8];
            const uint32_t* sw = (const uint32_t*)&us;
            const uint32_t* dw = (const uint32_t*)&ud;
            #pragma unroll
            for (int nt = 0; nt < 4; nt++) {
                float2 a = __half22float2(*(const __half2*)&sw[nt]);
                float2 b = __half22float2(*(const __half2*)&dw[nt]);
                c1[mt][nt][2*h]   = a.x + b.x;
                c1[mt][nt][2*h+1] = a.y + b.y;
            }
        }

        // ======== stage ef (64 rows) =======================================
        __syncwarp();
        #pragma unroll
        for (int i = 0; i < 32; i++) {
            int idx = i * 32 + lane;
            int row = idx >> 4, c16 = idx & 15;
            int r = eb + row; r = (r < E) ? r : (E - 1);
            float4 v = *(const float4*)&ef[(size_t)r * 64 + 4 * c16];
            uint2 w = { h2pack(v.x, v.y), h2pack(v.z, v.w) };
            *(uint2*)&buf[row * 36 + 2 * c16] = w;
        }
        __syncwarp();

        // ======== L1: K=64 -> 4 k16 chunks =================================
        #pragma unroll
        for (int kt = 0; kt < 4; kt++) {
            uint32_t a[4][4];
            #pragma unroll
            for (int mt = 0; mt < 4; mt++) {
                int r0 = (16*mt + g) * 36, r1 = (16*mt + 8 + g) * 36;
                a[mt][0] = buf[r0 + 8*kt + q];
                a[mt][1] = buf[r1 + 8*kt + q];
                a[mt][2] = buf[r0 + 8*kt + q + 4];
                a[mt][3] = buf[r1 + 8*kt + q + 4];
            }
            #pragma unroll
            for (int nt = 0; nt < 4; nt++) {
                uint32_t b0 = W1s[(8*nt+g)*36 + 8*kt + q];
                uint32_t b1 = W1s[(8*nt+g)*36 + 8*kt + q + 4];
                #pragma unroll
                for (int mt = 0; mt < 4; mt++)
                    mma16(c1[mt][nt], a[mt][0],a[mt][1],a[mt][2],a[mt][3], b0, b1);
            }
        }
        // ---- h1 C->A local packing (32 regs) -------------------------------
        uint32_t h1a[2][4][4];
        #pragma unroll
        for (int kc = 0; kc < 2; kc++)
            #pragma unroll
            for (int mt = 0; mt < 4; mt++) {
                h1a[kc][mt][0] = h2relu(c1[mt][2*kc][0],   c1[mt][2*kc][1]);
                h1a[kc][mt][1] = h2relu(c1[mt][2*kc][2],   c1[mt][2*kc][3]);
                h1a[kc][mt][2] = h2relu(c1[mt][2*kc+1][0], c1[mt][2*kc+1][1]);
                h1a[kc][mt][3] = h2relu(c1[mt][2*kc+1][2], c1[mt][2*kc+1][3]);
            }

        // ========== L2+L3 fused (em in 16-col chunks) ======================
        float c3[4][8][4];
        #pragma unroll
        for (int m = 0; m < 8; m++) {
            const int mt = m >> 1, h = m & 1;
            const __half* Pp = &g_P[(size_t)didx[m] * 128 + 64 + q * 16];
            uint4 p0 = *(const uint4*)Pp;
            uint4 p1 = *(const uint4*)(Pp + 8);
            const uint32_t* w0 = (const uint32_t*)&p0;
            const uint32_t* w1 = (const uint32_t*)&p1;
            #pragma unroll
            for (int nt = 0; nt < 4; nt++) {
                float2 a = __half22float2(*(const __half2*)&w0[nt]);
                float2 b = __half22float2(*(const __half2*)&w1[nt]);
                c3[mt][nt][2*h]   = a.x;  c3[mt][nt][2*h+1]   = a.y;
                c3[mt][nt+4][2*h] = b.x;  c3[mt][nt+4][2*h+1] = b.y;
            }
        }
        #pragma unroll
        for (int ch2 = 0; ch2 < 8; ch2++) {
            float c2[4][2][4];
            #pragma unroll
            for (int nt = 0; nt < 2; nt++) {
                float2 b = *(const float2*)&be2s[16*ch2 + 8*nt + 2*q];
                #pragma unroll
                for (int mt = 0; mt < 4; mt++) {
                    c2[mt][nt][0] = b.x; c2[mt][nt][1] = b.y;
                    c2[mt][nt][2] = b.x; c2[mt][nt][3] = b.y;
                }
            }
            #pragma unroll
            for (int kt = 0; kt < 2; kt++) {
                #pragma unroll
                for (int nt = 0; nt < 2; nt++) {
                    uint32_t b0 = W2s[(16*ch2 + 8*nt + g)*20 + 8*kt + q];
                    uint32_t b1 = W2s[(16*ch2 + 8*nt + g)*20 + 8*kt + q + 4];
                    #pragma unroll
                    for (int mt = 0; mt < 4; mt++)
                        mma16(c2[mt][nt], h1a[kt][mt][0],h1a[kt][mt][1],
                                          h1a[kt][mt][2],h1a[kt][mt][3], b0, b1);
                }
            }
            // em chunk (16 cols = 1 k16 group) -> A-frags, feed L3
            uint32_t a[4][4];
            #pragma unroll
            for (int mt = 0; mt < 4; mt++) {
                a[mt][0] = h2relu(c2[mt][0][0], c2[mt][0][1]);
                a[mt][1] = h2relu(c2[mt][0][2], c2[mt][0][3]);
                a[mt][2] = h2relu(c2[mt][1][0], c2[mt][1][1]);
                a[mt][3] = h2relu(c2[mt][1][2], c2[mt][1][3]);
            }
            #pragma unroll
            for (int nt = 0; nt < 8; nt++) {
                uint32_t b0 = W3s[(8*nt+g)*68 + 8*ch2 + q];
                uint32_t b1 = W3s[(8*nt+g)*68 + 8*ch2 + q + 4];
                #pragma unroll
                for (int mt = 0; mt < 4; mt++)
                    mma16(c3[mt][nt], a[mt][0],a[mt][1],a[mt][2],a[mt][3], b0, b1);
            }
        }

        // ---- h2 C->A local packing (64 regs; c3 dies here) ----------------
        uint32_t h2a[4][4][4];
        #pragma unroll
        for (int kc = 0; kc < 4; kc++)
            #pragma unroll
            for (int mt = 0; mt < 4; mt++) {
                h2a[kc][mt][0] = h2relu(c3[mt][2*kc][0],   c3[mt][2*kc][1]);
                h2a[kc][mt][1] = h2relu(c3[mt][2*kc][2],   c3[mt][2*kc][3]);
                h2a[kc][mt][2] = h2relu(c3[mt][2*kc+1][0], c3[mt][2*kc+1][1]);
                h2a[kc][mt][3] = h2relu(c3[mt][2*kc+1][2], c3[mt][2*kc+1][3]);
            }

        // ============ L4 (16-col chunks) + f16 swizzled scatter ============
        #pragma unroll
        for (int n4c = 0; n4c < 8; n4c++) {
            float c4[4][2][4];
            #pragma unroll
            for (int nt = 0; nt < 2; nt++) {
                float2 b = *(const float2*)&bn2s[16*n4c + 8*nt + 2*q];
                #pragma unroll
                for (int mt = 0; mt < 4; mt++) {
                    c4[mt][nt][0] = b.x; c4[mt][nt][1] = b.y;
                    c4[mt][nt][2] = b.x; c4[mt][nt][3] = b.y;
                }
            }
            #pragma unroll
            for (int kt = 0; kt < 4; kt++) {
                #pragma unroll
                for (int nt = 0; nt < 2; nt++) {
                    uint32_t b0 = W4s[(16*n4c + 8*nt + g)*36 + 8*kt + q];
                    uint32_t b1 = W4s[(16*n4c + 8*nt + g)*36 + 8*kt + q + 4];
                    #pragma unroll
                    for (int mt = 0; mt < 4; mt++)
                        mma16(c4[mt][nt], h2a[kt][mt][0],h2a[kt][mt][1],
                                          h2a[kt][mt][2],h2a[kt][mt][3], b0, b1);
                }
            }
            __syncwarp();
            // store nm chunk as f16x2 in swizzled [64 rows][8 words]
            const int soff = 4 * ((g >> 2) & 1);
            #pragma unroll
            for (int mt = 0; mt < 4; mt++)
                #pragma unroll
                for (int nt = 0; nt < 2; nt++) {
                    uint32_t v0 = h2relu(c4[mt][nt][0], c4[mt][nt][1]);
                    uint32_t v1 = h2relu(c4[mt][nt][2], c4[mt][nt][3]);
                    const int w = (4*nt + q + soff) & 7;
                    buf[(16*mt + g)     * 8 + w] = v0;
                    buf[(16*mt + 8 + g) * 8 + w] = v1;
                }
            __syncwarp();
            #pragma unroll
            for (int i = 0; i < 8; i++) {
                int row = 8 * i + (lane >> 2);
                int cc  = lane & 3;
                int w   = (2*cc + 4*((row >> 2) & 1)) & 7;
                uint2 vv = *(const uint2*)&buf[row * 8 + w];
                float2 f0 = __half22float2(*(const __half2*)&vv.x);
                float2 f1 = __half22float2(*(const __half2*)&vv.y);
                int dr = __shfl_sync(F, (i < 4) ? dl0 : dl1, row & 31);
                if (eb + row < E)
                    red4(out + (size_t)dr * 128 + 16 * n4c + 4 * cc,
                         f0.x, f0.y, f1.x, f1.y);
            }
        }
    }
}

// ---------------------------------------------------------------------------
extern "C" void kernel_launch(void* const* d_in, const int* in_sizes, int n_in,
                              void* d_out, int out_size) {
    const float* nf  = (const float*)d_in[0];
    const float* ef  = (const float*)d_in[1];
    const int*   ei  = (const int*)  d_in[2];
    const float* We1 = (const float*)d_in[3];
    const float* be1 = (const float*)d_in[4];
    const float* We2 = (const float*)d_in[5];
    const float* be2 = (const float*)d_in[6];
    const float* Wn1 = (const float*)d_in[7];
    const float* bn1 = (const float*)d_in[8];
    const float* Wn2 = (const float*)d_in[9];
    const float* bn2 = (const float*)d_in[10];
    float* out = (float*)d_out;

    const int Nn = in_sizes[0] / 128;
    const int E  = in_sizes[2] / 2;
    const int ntiles = (E + TILE_E - 1) / TILE_E;

    pack_weights_kernel<<<128, 256>>>(We1, We2, Wn1, Wn2);

    cudaFuncSetAttribute(precompute_mma_kernel,
                         cudaFuncAttributeMaxDynamicSharedMemorySize, P_SMEM);
    precompute_mma_kernel<<<(Nn + 255) / 256, P_TPB, P_SMEM>>>(
        nf, be1, bn1, out, Nn);

    cudaFuncSetAttribute(edge_mma_kernel,
                         cudaFuncAttributeMaxDynamicSharedMemorySize, SM_TOTAL);
    edge_mma_kernel<<<EGRID, TPB, SM_TOTAL>>>(ef, ei, be2, bn2, out, E, ntiles);
}

// round 17
// speedup vs baseline: 1.0696x; 1.0696x over previous
#include <cuda_runtime.h>
#include <cuda_fp16.h>
#include <cstdint>

#define TPB 256
#define NWARP 8
#define TILE_E (NWARP * 32)
#define EGRID 304
#define MAXN 50000

// Per-node precomputed projections in FP16, COLUMN-PERMUTED:
// slice0 [0:32)  = nf@We1[0:128]+be1 (src)
// slice1 [32:64) = nf@We1[128:256]   (dst)
// slice2 [64:128)= nf@Wn1[0:128]+bn1 (pre2)
__device__ __align__(16) __half g_P[MAXN * 128];

// Pre-packed weight images (bit-identical to the smem layouts, pitches incl.)
__device__ __align__(16) uint32_t g_Wpre[128 * 68];  // precompute [128 n][68 w]
__device__ __align__(16) uint32_t g_W1p[32 * 36];
__device__ __align__(16) uint32_t g_W2p[128 * 20];
__device__ __align__(16) uint32_t g_W3p[64 * 68];
__device__ __align__(16) uint32_t g_W4p[128 * 36];

// ------------------------------- helpers ----------------------------------
__device__ __forceinline__ uint32_t h2pack(float lo, float hi) {
    uint32_t r;  // cvt.rn.f16x2.f32 d, a, b -> d.hi = a, d.lo = b
    asm("cvt.rn.f16x2.f32 %0, %1, %2;" : "=r"(r) : "f"(hi), "f"(lo));
    return r;
}
__device__ __forceinline__ uint32_t h2relu(float c0, float c1) {
    return h2pack(fmaxf(c0, 0.f), fmaxf(c1, 0.f));
}
__device__ __forceinline__ void red4(float* p, float a, float b, float c, float d) {
    asm volatile("red.global.add.v4.f32 [%0], {%1,%2,%3,%4};"
                 :: "l"(p), "f"(a), "f"(b), "f"(c), "f"(d) : "memory");
}
// D(16x8,f32) += A(16x16,f16) @ B(16x8,f16)
__device__ __forceinline__ void mma16(float* c, uint32_t a0, uint32_t a1,
                                      uint32_t a2, uint32_t a3,
                                      uint32_t b0, uint32_t b1) {
    asm volatile("mma.sync.aligned.m16n8k16.row.col.f32.f16.f16.f32 "
                 "{%0,%1,%2,%3}, {%4,%5,%6,%7}, {%8,%9}, {%0,%1,%2,%3};"
                 : "+f"(c[0]), "+f"(c[1]), "+f"(c[2]), "+f"(c[3])
                 : "r"(a0), "r"(a1), "r"(a2), "r"(a3), "r"(b0), "r"(b1));
}

// ---------------------------------------------------------------------------
// Pack kernel: one-time scattered transpose + f16 pack of all weights.
// ---------------------------------------------------------------------------
__global__ void __launch_bounds__(256) pack_weights_kernel(
    const float* __restrict__ We1,
    const float* __restrict__ We2,
    const float* __restrict__ Wn1,
    const float* __restrict__ Wn2)
{
    const int tid = blockIdx.x * 256 + threadIdx.x;
    const int stride = gridDim.x * 256;

    for (int i = tid; i < 128 * 64; i += stride) {          // precompute block
        int n = i >> 6, w = i & 63;
        float lo, hi;
        if (n < 32)      { lo = We1[(2*w)*32 + n];         hi = We1[(2*w+1)*32 + n]; }
        else if (n < 64) { lo = We1[(128+2*w)*32 + n-32];  hi = We1[(128+2*w+1)*32 + n-32]; }
        else             { lo = Wn1[(2*w)*64 + n-64];      hi = Wn1[(2*w+1)*64 + n-64]; }
        g_Wpre[n*68 + w] = h2pack(lo, hi);
    }
    const float* W = We1 + 256 * 32;
    for (int i = tid; i < 32 * 32; i += stride) {
        int n = i >> 5, w = i & 31;
        g_W1p[n*36 + w] = h2pack(W[(2*w)*32 + n], W[(2*w+1)*32 + n]);
    }
    for (int i = tid; i < 128 * 16; i += stride) {
        int n = i >> 4, w = i & 15;
        g_W2p[n*20 + w] = h2pack(We2[(2*w)*128 + n], We2[(2*w+1)*128 + n]);
    }
    const float* W3 = Wn1 + 128 * 64;
    for (int i = tid; i < 64 * 64; i += stride) {
        int n = i >> 6, w = i & 63;
        g_W3p[n*68 + w] = h2pack(W3[(2*w)*64 + n], W3[(2*w+1)*64 + n]);
    }
    for (int i = tid; i < 128 * 32; i += stride) {
        int n = i >> 5, w = i & 31;
        g_W4p[n*36 + w] = h2pack(Wn2[(2*w)*128 + n], Wn2[(2*w+1)*128 + n]);
    }
}

// ---------------------------------------------------------------------------
// Precompute via mma16 (R15 version, unchanged): 32 nodes/warp, 256/CTA.
// ---------------------------------------------------------------------------
#define P_TPB 256
#define P_WSMEM 8704
#define P_OFF_B 34816
#define P_OFF_SCR 35328
#define P_SMEM (P_OFF_SCR + 8 * P_WSMEM)   // 104960

__global__ void __launch_bounds__(P_TPB, 1) precompute_mma_kernel(
    const float* __restrict__ nf,
    const float* __restrict__ be1,
    const float* __restrict__ bn1,
    float* __restrict__ out, int Nn)
{
    extern __shared__ char sm[];
    uint32_t* Wp = (uint32_t*)sm;
    float* bias  = (float*)(sm + P_OFF_B);

    const int tid = threadIdx.x;
    {
        const uint4* src = (const uint4*)g_Wpre;
        uint4* dst = (uint4*)Wp;
        for (int i = tid; i < (128 * 68) / 4; i += P_TPB) dst[i] = src[i];
    }
    if (tid < 128)
        bias[tid] = (tid < 32) ? be1[tid] : ((tid < 64) ? 0.f : bn1[tid - 64]);
    __syncthreads();

    const int lane = tid & 31, wid = tid >> 5;
    const int g = lane >> 2, q = lane & 3;
    uint32_t* buf = (uint32_t*)(sm + P_OFF_SCR + wid * P_WSMEM);

    const int nb = blockIdx.x * 256 + wid * 32;

    #pragma unroll
    for (int it = 0; it < 32; it++) {
        int idx = it * 32 + lane;
        int row = idx >> 5, c = idx & 31;
        int n = nb + row;
        if (n < Nn) {
            float4 v = *(const float4*)&nf[(size_t)n * 128 + 4 * c];
            *(float4*)&out[(size_t)n * 128 + 4 * c] = v;
            uint2 w = { h2pack(v.x, v.y), h2pack(v.z, v.w) };
            *(uint2*)&buf[row * 68 + 2 * c] = w;
        } else {
            *(uint2*)&buf[row * 68 + 2 * c] = make_uint2(0, 0);
        }
    }
    __syncwarp();

    float c[2][16][4];
    #pragma unroll
    for (int nt = 0; nt < 16; nt++) {
        float2 b = *(const float2*)&bias[8 * nt + 2 * q];
        #pragma unroll
        for (int mt = 0; mt < 2; mt++) {
            c[mt][nt][0] = b.x; c[mt][nt][1] = b.y;
            c[mt][nt][2] = b.x; c[mt][nt][3] = b.y;
        }
    }
    #pragma unroll
    for (int kt = 0; kt < 8; kt++) {
        uint32_t a[2][4];
        #pragma unroll
        for (int mt = 0; mt < 2; mt++) {
            int r0 = (16*mt + g) * 68, r1 = (16*mt + 8 + g) * 68;
            a[mt][0] = buf[r0 + 8*kt + q];
            a[mt][1] = buf[r1 + 8*kt + q];
            a[mt][2] = buf[r0 + 8*kt + q + 4];
            a[mt][3] = buf[r1 + 8*kt + q + 4];
        }
        #pragma unroll
        for (int nt = 0; nt < 16; nt++) {
            uint32_t b0 = Wp[(8*nt+g)*68 + 8*kt + q];
            uint32_t b1 = Wp[(8*nt+g)*68 + 8*kt + q + 4];
            mma16(c[0][nt], a[0][0],a[0][1],a[0][2],a[0][3], b0, b1);
            mma16(c[1][nt], a[1][0],a[1][1],a[1][2],a[1][3], b0, b1);
        }
    }
    #pragma unroll
    for (int nt = 0; nt < 16; nt++) {
        int word = (nt < 4)  ? (q*4 + nt)
                 : (nt < 8)  ? (16 + q*4 + (nt - 4))
                 :             (32 + q*8 + (nt - 8));
        #pragma unroll
        for (int mt = 0; mt < 2; mt++) {
            int n0 = nb + 16*mt + g, n1 = nb + 16*mt + 8 + g;
            if (n0 < Nn)
                ((uint32_t*)&g_P[(size_t)n0 * 128])[word] = h2pack(c[mt][nt][0], c[mt][nt][1]);
            if (n1 < Nn)
                ((uint32_t*)&g_P[(size_t)n1 * 128])[word] = h2pack(c[mt][nt][2], c[mt][nt][3]);
        }
    }
}

// ---------------------------------------------------------------------------
// Edge kernel: persistent, 8 warps x 32 edges, 2 CTAs/SM (16 warps/SM).
// L2 and L4 chunked to 16 columns to keep peak live regs < 128 (no spills).
// Scatter per 16-col chunk: f16x2 swizzled [32][8] smem -> coalesced red4.
// ---------------------------------------------------------------------------
#define OFF_W1  0            // [32 n][36 w]  -> 4608 B
#define OFF_W2  4608         // [128][20]     -> 10240 B
#define OFF_W3  14848        // [64][68]      -> 17408 B
#define OFF_W4  32256        // [128][36]     -> 18432 B
#define OFF_BE2 50688
#define OFF_BN2 51200
#define OFF_SCR 51712
#define WS_BYTES 4608        // per-warp buffer (ef f16 staging / nm f16 scatter)
#define SM_TOTAL (OFF_SCR + NWARP * WS_BYTES)   // 88576

__global__ void __launch_bounds__(TPB, 2) edge_mma_kernel(
    const float* __restrict__ ef,
    const int*   __restrict__ eidx,
    const float* __restrict__ be2,
    const float* __restrict__ bn2,
    float* __restrict__ out, int E, int ntiles)
{
    extern __shared__ char sm[];
    uint32_t* W1s = (uint32_t*)(sm + OFF_W1);
    uint32_t* W2s = (uint32_t*)(sm + OFF_W2);
    uint32_t* W3s = (uint32_t*)(sm + OFF_W3);
    uint32_t* W4s = (uint32_t*)(sm + OFF_W4);
    float* be2s = (float*)(sm + OFF_BE2);
    float* bn2s = (float*)(sm + OFF_BN2);

    const int tid = threadIdx.x;
    {
        const uint4* s1 = (const uint4*)g_W1p;
        const uint4* s2 = (const uint4*)g_W2p;
        const uint4* s3 = (const uint4*)g_W3p;
        const uint4* s4 = (const uint4*)g_W4p;
        for (int i = tid; i < 288;  i += TPB) ((uint4*)(sm + OFF_W1))[i] = s1[i];
        for (int i = tid; i < 640;  i += TPB) ((uint4*)(sm + OFF_W2))[i] = s2[i];
        for (int i = tid; i < 1088; i += TPB) ((uint4*)(sm + OFF_W3))[i] = s3[i];
        for (int i = tid; i < 1152; i += TPB) ((uint4*)(sm + OFF_W4))[i] = s4[i];
    }
    if (tid < 128) { be2s[tid] = be2[tid]; bn2s[tid] = bn2[tid]; }
    __syncthreads();

    const int lane = tid & 31, wid = tid >> 5;
    const int g = lane >> 2, q = lane & 3;
    const unsigned F = 0xFFFFFFFFu;
    uint32_t* buf = (uint32_t*)(sm + OFF_SCR + wid * WS_BYTES);

    for (int t = blockIdx.x; t < ntiles; t += gridDim.x) {
        const int eb = t * TILE_E + wid * 32;

        int sidx[4], didx[4];
        #pragma unroll
        for (int m = 0; m < 4; m++) {
            int r = eb + 16 * (m >> 1) + 8 * (m & 1) + g;
            r = (r < E) ? r : (E - 1);
            sidx[m] = eidx[r];
            didx[m] = eidx[E + r];
        }
        int rl = eb + lane; rl = (rl < E) ? rl : (E - 1);
        const int dl = eidx[E + rl];

        // ======== L1 init: c1 = pre1 =======================================
        float c1[2][4][4];
        #pragma unroll
        for (int m = 0; m < 4; m++) {
            const int mt = m >> 1, h = m & 1;
            uint4 us = *(const uint4*)&g_P[(size_t)sidx[m] * 128 + q * 8];
            uint4 ud = *(const uint4*)&g_P[(size_t)didx[m] * 128 + 32 + q * 8];
            const uint32_t* sw = (const uint32_t*)&us;
            const uint32_t* dw = (const uint32_t*)&ud;
            #pragma unroll
            for (int nt = 0; nt < 4; nt++) {
                float2 a = __half22float2(*(const __half2*)&sw[nt]);
                float2 b = __half22float2(*(const __half2*)&dw[nt]);
                c1[mt][nt][2*h]   = a.x + b.x;
                c1[mt][nt][2*h+1] = a.y + b.y;
            }
        }

        // ======== stage ef =================================================
        __syncwarp();
        #pragma unroll
        for (int i = 0; i < 16; i++) {
            int idx = i * 32 + lane;
            int row = idx >> 4, c16 = idx & 15;
            int r = eb + row; r = (r < E) ? r : (E - 1);
            float4 v = *(const float4*)&ef[(size_t)r * 64 + 4 * c16];
            uint2 w = { h2pack(v.x, v.y), h2pack(v.z, v.w) };
            *(uint2*)&buf[row * 36 + 2 * c16] = w;
        }
        __syncwarp();

        // ======== L1: K=64 -> 4 k16 chunks =================================
        #pragma unroll
        for (int kt = 0; kt < 4; kt++) {
            uint32_t a[2][4];
            #pragma unroll
            for (int mt = 0; mt < 2; mt++) {
                int r0 = (16*mt + g) * 36, r1 = (16*mt + 8 + g) * 36;
                a[mt][0] = buf[r0 + 8*kt + q];
                a[mt][1] = buf[r1 + 8*kt + q];
                a[mt][2] = buf[r0 + 8*kt + q + 4];
                a[mt][3] = buf[r1 + 8*kt + q + 4];
            }
            #pragma unroll
            for (int nt = 0; nt < 4; nt++) {
                uint32_t b0 = W1s[(8*nt+g)*36 + 8*kt + q];
                uint32_t b1 = W1s[(8*nt+g)*36 + 8*kt + q + 4];
                mma16(c1[0][nt], a[0][0],a[0][1],a[0][2],a[0][3], b0, b1);
                mma16(c1[1][nt], a[1][0],a[1][1],a[1][2],a[1][3], b0, b1);
            }
        }
        // ---- h1 C->A local packing ----------------------------------------
        uint32_t h1a[2][2][4];
        #pragma unroll
        for (int kc = 0; kc < 2; kc++)
            #pragma unroll
            for (int mt = 0; mt < 2; mt++) {
                h1a[kc][mt][0] = h2relu(c1[mt][2*kc][0],   c1[mt][2*kc][1]);
                h1a[kc][mt][1] = h2relu(c1[mt][2*kc][2],   c1[mt][2*kc][3]);
                h1a[kc][mt][2] = h2relu(c1[mt][2*kc+1][0], c1[mt][2*kc+1][1]);
                h1a[kc][mt][3] = h2relu(c1[mt][2*kc+1][2], c1[mt][2*kc+1][3]);
            }

        // ========== L2+L3 fused (em in 16-col chunks, low reg peak) ========
        float c3[2][8][4];
        #pragma unroll
        for (int m = 0; m < 4; m++) {
            const int mt = m >> 1, h = m & 1;
            const __half* Pp = &g_P[(size_t)didx[m] * 128 + 64 + q * 16];
            uint4 p0 = *(const uint4*)Pp;
            uint4 p1 = *(const uint4*)(Pp + 8);
            const uint32_t* w0 = (const uint32_t*)&p0;
            const uint32_t* w1 = (const uint32_t*)&p1;
            #pragma unroll
            for (int nt = 0; nt < 4; nt++) {
                float2 a = __half22float2(*(const __half2*)&w0[nt]);
                float2 b = __half22float2(*(const __half2*)&w1[nt]);
                c3[mt][nt][2*h]   = a.x;  c3[mt][nt][2*h+1]   = a.y;
                c3[mt][nt+4][2*h] = b.x;  c3[mt][nt+4][2*h+1] = b.y;
            }
        }
        #pragma unroll
        for (int ch2 = 0; ch2 < 8; ch2++) {
            float c2[2][2][4];
            #pragma unroll
            for (int nt = 0; nt < 2; nt++) {
                float2 b = *(const float2*)&be2s[16*ch2 + 8*nt + 2*q];
                #pragma unroll
                for (int mt = 0; mt < 2; mt++) {
                    c2[mt][nt][0] = b.x; c2[mt][nt][1] = b.y;
                    c2[mt][nt][2] = b.x; c2[mt][nt][3] = b.y;
                }
            }
            #pragma unroll
            for (int kt = 0; kt < 2; kt++) {
                #pragma unroll
                for (int nt = 0; nt < 2; nt++) {
                    uint32_t b0 = W2s[(16*ch2 + 8*nt + g)*20 + 8*kt + q];
                    uint32_t b1 = W2s[(16*ch2 + 8*nt + g)*20 + 8*kt + q + 4];
                    mma16(c2[0][nt], h1a[kt][0][0],h1a[kt][0][1],h1a[kt][0][2],h1a[kt][0][3], b0, b1);
                    mma16(c2[1][nt], h1a[kt][1][0],h1a[kt][1][1],h1a[kt][1][2],h1a[kt][1][3], b0, b1);
                }
            }
            // em chunk (16 cols = one k16 group) -> A-frags, feed L3
            uint32_t a[2][4];
            #pragma unroll
            for (int mt = 0; mt < 2; mt++) {
                a[mt][0] = h2relu(c2[mt][0][0], c2[mt][0][1]);
                a[mt][1] = h2relu(c2[mt][0][2], c2[mt][0][3]);
                a[mt][2] = h2relu(c2[mt][1][0], c2[mt][1][1]);
                a[mt][3] = h2relu(c2[mt][1][2], c2[mt][1][3]);
            }
            #pragma unroll
            for (int nt = 0; nt < 8; nt++) {
                uint32_t b0 = W3s[(8*nt+g)*68 + 8*ch2 + q];
                uint32_t b1 = W3s[(8*nt+g)*68 + 8*ch2 + q + 4];
                mma16(c3[0][nt], a[0][0],a[0][1],a[0][2],a[0][3], b0, b1);
                mma16(c3[1][nt], a[1][0],a[1][1],a[1][2],a[1][3], b0, b1);
            }
        }

        // ---- h2 C->A local packing (c3 dies here) --------------------------
        uint32_t h2a[4][2][4];
        #pragma unroll
        for (int kc = 0; kc < 4; kc++)
            #pragma unroll
            for (int mt = 0; mt < 2; mt++) {
                h2a[kc][mt][0] = h2relu(c3[mt][2*kc][0],   c3[mt][2*kc][1]);
                h2a[kc][mt][1] = h2relu(c3[mt][2*kc][2],   c3[mt][2*kc][3]);
                h2a[kc][mt][2] = h2relu(c3[mt][2*kc+1][0], c3[mt][2*kc+1][1]);
                h2a[kc][mt][3] = h2relu(c3[mt][2*kc+1][2], c3[mt][2*kc+1][3]);
            }

        // ============ L4 (16-col chunks) + f16 swizzled scatter ============
        #pragma unroll
        for (int n4c = 0; n4c < 8; n4c++) {
            float c4[2][2][4];
            #pragma unroll
            for (int nt = 0; nt < 2; nt++) {
                float2 b = *(const float2*)&bn2s[16*n4c + 8*nt + 2*q];
                #pragma unroll
                for (int mt = 0; mt < 2; mt++) {
                    c4[mt][nt][0] = b.x; c4[mt][nt][1] = b.y;
                    c4[mt][nt][2] = b.x; c4[mt][nt][3] = b.y;
                }
            }
            #pragma unroll
            for (int kt = 0; kt < 4; kt++) {
                #pragma unroll
                for (int nt = 0; nt < 2; nt++) {
                    uint32_t b0 = W4s[(16*n4c + 8*nt + g)*36 + 8*kt + q];
                    uint32_t b1 = W4s[(16*n4c + 8*nt + g)*36 + 8*kt + q + 4];
                    mma16(c4[0][nt], h2a[kt][0][0],h2a[kt][0][1],h2a[kt][0][2],h2a[kt][0][3], b0, b1);
                    mma16(c4[1][nt], h2a[kt][1][0],h2a[kt][1][1],h2a[kt][1][2],h2a[kt][1][3], b0, b1);
                }
            }
            __syncwarp();
            // store nm chunk as f16x2 into swizzled [32 rows][8 words]
            #pragma unroll
            for (int mt = 0; mt < 2; mt++)
                #pragma unroll
                for (int nt = 0; nt < 2; nt++) {
                    uint32_t v0 = h2relu(c4[mt][nt][0], c4[mt][nt][1]);
                    uint32_t v1 = h2relu(c4[mt][nt][2], c4[mt][nt][3]);
                    const int s = 4 * ((g >> 2) & 1);     // same for row & row+8
                    const int w = (4*nt + q + s) & 7;
                    buf[(16*mt + g)     * 8 + w] = v0;
                    buf[(16*mt + 8 + g) * 8 + w] = v1;
                }
            __syncwarp();
            #pragma unroll
            for (int i = 0; i < 4; i++) {
                int row = 8 * i + (lane >> 2);
                int cc  = lane & 3;
                int w   = (2*cc + 4*((row >> 2) & 1)) & 7;
                uint2 vv = *(const uint2*)&buf[row * 8 + w];
                float2 f0 = __half22float2(*(const __half2*)&vv.x);
                float2 f1 = __half22float2(*(const __half2*)&vv.y);
                int dr = __shfl_sync(F, dl, row);
                if (eb + row < E)
                    red4(out + (size_t)dr * 128 + 16 * n4c + 4 * cc,
                         f0.x, f0.y, f1.x, f1.y);
            }
        }
    }
}

// ---------------------------------------------------------------------------
extern "C" void kernel_launch(void* const* d_in, const int* in_sizes, int n_in,
                              void* d_out, int out_size) {
    const float* nf  = (const float*)d_in[0];
    const float* ef  = (const float*)d_in[1];
    const int*   ei  = (const int*)  d_in[2];
    const float* We1 = (const float*)d_in[3];
    const float* be1 = (const float*)d_in[4];
    const float* We2 = (const float*)d_in[5];
    const float* be2 = (const float*)d_in[6];
    const float* Wn1 = (const float*)d_in[7];
    const float* bn1 = (const float*)d_in[8];
    const float* Wn2 = (const float*)d_in[9];
    const float* bn2 = (const float*)d_in[10];
    float* out = (float*)d_out;

    const int Nn = in_sizes[0] / 128;
    const int E  = in_sizes[2] / 2;
    const int ntiles = (E + TILE_E - 1) / TILE_E;

    pack_weights_kernel<<<128, 256>>>(We1, We2, Wn1, Wn2);

    cudaFuncSetAttribute(precompute_mma_kernel,
                         cudaFuncAttributeMaxDynamicSharedMemorySize, P_SMEM);
    precompute_mma_kernel<<<(Nn + 255) / 256, P_TPB, P_SMEM>>>(
        nf, be1, bn1, out, Nn);

    cudaFuncSetAttribute(edge_mma_kernel,
                         cudaFuncAttributeMaxDynamicSharedMemorySize, SM_TOTAL);
    edge_mma_kernel<<<EGRID, TPB, SM_TOTAL>>>(ef, ei, be2, bn2, out, E, ntiles);
}